// round 9
// baseline (speedup 1.0000x reference)
#include <cuda_runtime.h>
#include <cuda_fp16.h>

// ---------------------------------------------------------------------------
// JKNet: 3x GraphConv(norm='both') + JK-cat + sum-pool + linear.
//
//   out = segment_sum((jk @ Wo)[src], dst) + bo          (linearity)
//   jk @ Wo = h1 @ Wo[0:128] + h2 @ Wo[128:256] + h3 @ Wo[256:384]
//
// R8 changes vs R7 (gemm was latency-bound: occ 28%, fma 42%):
//   * Split-K GEMM tiling: one 64x68 smem chunk (17.4KB) reused for two
//     64-wide K chunks -> 13 blocks/SM (81% occ) instead of 6 (37%).
//   * Tile reads vectorized: 4x LDS.128 per k instead of 8x LDS.64
//     (PITCH 66 -> 68 for 16B alignment). Halves shared-pipe wavefronts.
// ---------------------------------------------------------------------------

#define N_MAX 100000
#define E_MAX 1600000
#define SCAN_B 1024
#define PITCH 68   // floats per k-row of transposed tile (64 + 4 pad, 16B-aligned)

__device__ int   g_out_deg[N_MAX];
__device__ int   g_in_deg [N_MAX];
__device__ float g_out_norm[N_MAX];
__device__ float g_in_norm [N_MAX];
__device__ int   g_row_start[N_MAX + 1];
__device__ int   g_cursor[N_MAX];
__device__ int   g_esrc[E_MAX];
__device__ int   g_bsums[1024];
__device__ int   g_boff [1024];

__device__ uint4 g_yh[N_MAX * 16];   // y fp16: 128 cols = 16 uint4/row
__device__ uint2 g_zh[N_MAX * 16];   // z fp16:  64 cols = 16 uint2/row
__device__ float g_h1[N_MAX * 128];
__device__ float g_h2[N_MAX * 128];
__device__ float g_h3[N_MAX * 128];

// ---------------------------------------------------------------------------
// f32x2 packed-math helpers (ptxas never emits these from C++)
// ---------------------------------------------------------------------------

__device__ __forceinline__ unsigned long long pack2(float a, float b) {
    unsigned long long r;
    asm("mov.b64 %0, {%1, %2};" : "=l"(r) : "f"(a), "f"(b));
    return r;
}
__device__ __forceinline__ void unpack2(unsigned long long p, float& a, float& b) {
    asm("mov.b64 {%0, %1}, %2;" : "=f"(a), "=f"(b) : "l"(p));
}
__device__ __forceinline__ unsigned long long fma2(unsigned long long a,
                                                   unsigned long long b,
                                                   unsigned long long c) {
    unsigned long long d;
    asm("fma.rn.f32x2 %0, %1, %2, %3;" : "=l"(d) : "l"(a), "l"(b), "l"(c));
    return d;
}

// ---------------------------------------------------------------------------
// Degree / norm / CSR build
// ---------------------------------------------------------------------------

__global__ void k_zero_deg(int n) {
    int i = blockIdx.x * blockDim.x + threadIdx.x;
    if (i < n) { g_out_deg[i] = 0; g_in_deg[i] = 0; }
}

__global__ void k_count(const int* __restrict__ src, const int* __restrict__ dst, int e) {
    int i = blockIdx.x * blockDim.x + threadIdx.x;
    if (i < e) {
        atomicAdd(&g_out_deg[src[i]], 1);
        atomicAdd(&g_in_deg [dst[i]], 1);
    }
}

__global__ void k_norm(int n) {
    int i = blockIdx.x * blockDim.x + threadIdx.x;
    if (i < n) {
        float od = (float)g_out_deg[i];
        float id = (float)g_in_deg[i];
        g_out_norm[i] = od > 0.f ? rsqrtf(od) : 0.f;
        g_in_norm [i] = id > 0.f ? rsqrtf(id) : 0.f;
    }
}

__device__ __forceinline__ int block_excl_scan(int v, int* warp_sums) {
    int t = threadIdx.x, lane = t & 31, w = t >> 5;
    int x = v;
#pragma unroll
    for (int o = 1; o < 32; o <<= 1) {
        int y = __shfl_up_sync(0xffffffff, x, o);
        if (lane >= o) x += y;
    }
    if (lane == 31) warp_sums[w] = x;
    __syncthreads();
    if (w == 0) {
        int s = warp_sums[lane];
#pragma unroll
        for (int o = 1; o < 32; o <<= 1) {
            int y = __shfl_up_sync(0xffffffff, s, o);
            if (lane >= o) s += y;
        }
        warp_sums[lane] = s;
    }
    __syncthreads();
    int woff = (w > 0) ? warp_sums[w - 1] : 0;
    return woff + x - v;
}

__global__ void __launch_bounds__(1024) k_bsums(int n) {
    __shared__ int ws[32];
    int i = blockIdx.x * SCAN_B + threadIdx.x;
    int v = (i < n) ? g_in_deg[i] : 0;
    int lane = threadIdx.x & 31, w = threadIdx.x >> 5;
#pragma unroll
    for (int o = 16; o > 0; o >>= 1) v += __shfl_down_sync(0xffffffff, v, o);
    if (lane == 0) ws[w] = v;
    __syncthreads();
    if (w == 0) {
        int s = ws[lane];
#pragma unroll
        for (int o = 16; o > 0; o >>= 1) s += __shfl_down_sync(0xffffffff, s, o);
        if (lane == 0) g_bsums[blockIdx.x] = s;
    }
}

__global__ void __launch_bounds__(1024) k_scan_bsums(int nb) {
    __shared__ int ws[32];
    int t = threadIdx.x;
    int v = (t < nb) ? g_bsums[t] : 0;
    int ex = block_excl_scan(v, ws);
    if (t < nb) g_boff[t] = ex;
}

__global__ void __launch_bounds__(1024) k_write_csr(int n) {
    __shared__ int ws[32];
    int i = blockIdx.x * SCAN_B + threadIdx.x;
    int v = (i < n) ? g_in_deg[i] : 0;
    int ex = block_excl_scan(v, ws) + g_boff[blockIdx.x];
    if (i < n) {
        g_row_start[i] = ex;
        g_cursor[i]    = ex;
        if (i == n - 1) g_row_start[n] = ex + v;
    }
}

__global__ void k_fill(const int* __restrict__ src, const int* __restrict__ dst, int e) {
    int i = blockIdx.x * blockDim.x + threadIdx.x;
    if (i < e) {
        int p = atomicAdd(&g_cursor[dst[i]], 1);
        g_esrc[p] = src[i];
    }
}

// ---------------------------------------------------------------------------
// Transposed 64-k x-tile loader: sx[k - kc][r] (pitch PITCH), 64 rows.
// kq0 = kc/4 (float4 offset of the chunk within the 128-wide row).
// ---------------------------------------------------------------------------

__device__ __forceinline__ void load_tile_T64(const float4* __restrict__ x4,
                                              float* __restrict__ sx,
                                              int row0, int kq0, int n) {
    int tid = threadIdx.x;
    for (int i = tid; i < 64 * 16; i += 128) {
        int r  = i & 63;
        int kq = i >> 6;                  // 0..15 within the chunk
        float4 v = make_float4(0.f, 0.f, 0.f, 0.f);
        if (row0 + r < n) v = x4[(row0 + r) * 32 + kq0 + kq];
        int kb = 4 * kq;
        sx[(kb + 0) * PITCH + r] = v.x;
        sx[(kb + 1) * PITCH + r] = v.y;
        sx[(kb + 2) * PITCH + r] = v.z;
        sx[(kb + 3) * PITCH + r] = v.w;
    }
}

// ---------------------------------------------------------------------------
// GEMM: y[r,:] = fp16( out_norm[r] * (x[r,:] @ W) ),  x:[n,128], W:[128,128]
// 128 threads, 64 rows/block, 16 rows/warp, lane owns 4 cols.
// K split into two 64-chunks sharing one 17.4KB smem tile (13 blocks/SM).
// ---------------------------------------------------------------------------

__global__ void __launch_bounds__(128) gemm_layer(const float* __restrict__ x,
                                                  const float* __restrict__ W,
                                                  uint2* __restrict__ yh, int n) {
    __shared__ float sx[64 * PITCH];
    int tid  = threadIdx.x;
    int lane = tid & 31;
    int w    = tid >> 5;
    int row0 = blockIdx.x * 64;
    int rbase = w * 16;

    const float4* W4 = (const float4*)W;
    unsigned long long acc[8][4];
#pragma unroll
    for (int rp = 0; rp < 8; ++rp)
#pragma unroll
        for (int c = 0; c < 4; ++c) acc[rp][c] = 0ull;

    for (int kc = 0; kc < 128; kc += 64) {
        __syncthreads();
        load_tile_T64((const float4*)x, sx, row0, kc >> 2, n);
        __syncthreads();

#pragma unroll 2
        for (int k = 0; k < 64; ++k) {
            float4 wv = __ldg(&W4[(kc + k) * 32 + lane]);
            unsigned long long wd0 = pack2(wv.x, wv.x);
            unsigned long long wd1 = pack2(wv.y, wv.y);
            unsigned long long wd2 = pack2(wv.z, wv.z);
            unsigned long long wd3 = pack2(wv.w, wv.w);
            const ulonglong2* xr = (const ulonglong2*)(sx + k * PITCH + rbase);
            ulonglong2 x01 = xr[0];
            ulonglong2 x23 = xr[1];
            ulonglong2 x45 = xr[2];
            ulonglong2 x67 = xr[3];
            unsigned long long xp[8] = { x01.x, x01.y, x23.x, x23.y,
                                         x45.x, x45.y, x67.x, x67.y };
#pragma unroll
            for (int rp = 0; rp < 8; ++rp) {
                acc[rp][0] = fma2(xp[rp], wd0, acc[rp][0]);
                acc[rp][1] = fma2(xp[rp], wd1, acc[rp][1]);
                acc[rp][2] = fma2(xp[rp], wd2, acc[rp][2]);
                acc[rp][3] = fma2(xp[rp], wd3, acc[rp][3]);
            }
        }
    }

#pragma unroll
    for (int rp = 0; rp < 8; ++rp) {
        int ra = row0 + rbase + 2 * rp;
        float a0, e0, a1, e1, a2, e2, a3, e3;
        unpack2(acc[rp][0], a0, e0);
        unpack2(acc[rp][1], a1, e1);
        unpack2(acc[rp][2], a2, e2);
        unpack2(acc[rp][3], a3, e3);
        if (ra < n) {
            float s = g_out_norm[ra];
            __half2 p0 = __floats2half2_rn(a0 * s, a1 * s);
            __half2 p1 = __floats2half2_rn(a2 * s, a3 * s);
            uint2 u;
            u.x = *(unsigned*)&p0;
            u.y = *(unsigned*)&p1;
            yh[ra * 32 + lane] = u;
        }
        if (ra + 1 < n) {
            float s = g_out_norm[ra + 1];
            __half2 p0 = __floats2half2_rn(e0 * s, e1 * s);
            __half2 p1 = __floats2half2_rn(e2 * s, e3 * s);
            uint2 u;
            u.x = *(unsigned*)&p0;
            u.y = *(unsigned*)&p1;
            yh[(ra + 1) * 32 + lane] = u;
        }
    }
}

// ---------------------------------------------------------------------------
// Aggregation (128-wide): half-warp per node. Lane16 owns 8 cols (uint4).
// ---------------------------------------------------------------------------

__device__ __forceinline__ void add_h8(float* acc, uint4 u) {
    float2 f0 = __half22float2(*(__half2*)&u.x);
    float2 f1 = __half22float2(*(__half2*)&u.y);
    float2 f2 = __half22float2(*(__half2*)&u.z);
    float2 f3 = __half22float2(*(__half2*)&u.w);
    acc[0] += f0.x; acc[1] += f0.y; acc[2] += f1.x; acc[3] += f1.y;
    acc[4] += f2.x; acc[5] += f2.y; acc[6] += f3.x; acc[7] += f3.y;
}

__global__ void __launch_bounds__(256) agg128(const uint4* __restrict__ yh4,
                                              const float* __restrict__ bias,
                                              float* __restrict__ h, int n) {
    int node = (blockIdx.x * blockDim.x + threadIdx.x) >> 4;
    int l    = threadIdx.x & 15;
    if (node >= n) return;

    int s0 = g_row_start[node];
    int s1 = g_row_start[node + 1];

    float acc[8] = {0.f, 0.f, 0.f, 0.f, 0.f, 0.f, 0.f, 0.f};
    int e = s0;
    for (; e + 4 <= s1; e += 4) {
        int i0 = __ldg(&g_esrc[e]);
        int i1 = __ldg(&g_esrc[e + 1]);
        int i2 = __ldg(&g_esrc[e + 2]);
        int i3 = __ldg(&g_esrc[e + 3]);
        uint4 a = yh4[i0 * 16 + l];
        uint4 b = yh4[i1 * 16 + l];
        uint4 c = yh4[i2 * 16 + l];
        uint4 d = yh4[i3 * 16 + l];
        add_h8(acc, a); add_h8(acc, b); add_h8(acc, c); add_h8(acc, d);
    }
    for (; e < s1; ++e) {
        uint4 a = yh4[__ldg(&g_esrc[e]) * 16 + l];
        add_h8(acc, a);
    }

    float nv = g_in_norm[node];
    float4 b0 = ((const float4*)bias)[2 * l];
    float4 b1 = ((const float4*)bias)[2 * l + 1];
    float4 o0, o1;
    o0.x = fmaxf(acc[0] * nv + b0.x, 0.f);
    o0.y = fmaxf(acc[1] * nv + b0.y, 0.f);
    o0.z = fmaxf(acc[2] * nv + b0.z, 0.f);
    o0.w = fmaxf(acc[3] * nv + b0.w, 0.f);
    o1.x = fmaxf(acc[4] * nv + b1.x, 0.f);
    o1.y = fmaxf(acc[5] * nv + b1.y, 0.f);
    o1.z = fmaxf(acc[6] * nv + b1.z, 0.f);
    o1.w = fmaxf(acc[7] * nv + b1.w, 0.f);
    ((float4*)h)[node * 32 + 2 * l]     = o0;
    ((float4*)h)[node * 32 + 2 * l + 1] = o1;
}

// ---------------------------------------------------------------------------
// z = fp16( h1 @ Wo[0:128] + h2 @ Wo[128:256] + h3 @ Wo[256:384] )   (z: [n,64])
// Same split-K scheme (3 parts x 2 chunks); lane owns 2 cols.
// ---------------------------------------------------------------------------

__global__ void __launch_bounds__(128) gemm_z(const float* __restrict__ h1,
                                              const float* __restrict__ h2,
                                              const float* __restrict__ h3,
                                              const float* __restrict__ Wo,
                                              unsigned* __restrict__ zh, int n) {
    __shared__ float sx[64 * PITCH];
    int tid  = threadIdx.x;
    int lane = tid & 31;
    int w    = tid >> 5;
    int row0 = blockIdx.x * 64;
    int rbase = w * 16;

    unsigned long long acc[8][2];
#pragma unroll
    for (int rp = 0; rp < 8; ++rp) { acc[rp][0] = 0ull; acc[rp][1] = 0ull; }

    const float* parts[3] = { h1, h2, h3 };

    for (int p = 0; p < 3; ++p) {
        for (int kc = 0; kc < 128; kc += 64) {
            __syncthreads();
            load_tile_T64((const float4*)parts[p], sx, row0, kc >> 2, n);
            __syncthreads();

            const float2* Wp = (const float2*)Wo + (p * 128) * 32;
#pragma unroll 2
            for (int k = 0; k < 64; ++k) {
                float2 wv = __ldg(&Wp[(kc + k) * 32 + lane]);
                unsigned long long wd0 = pack2(wv.x, wv.x);
                unsigned long long wd1 = pack2(wv.y, wv.y);
                const ulonglong2* xr = (const ulonglong2*)(sx + k * PITCH + rbase);
                ulonglong2 x01 = xr[0];
                ulonglong2 x23 = xr[1];
                ulonglong2 x45 = xr[2];
                ulonglong2 x67 = xr[3];
                unsigned long long xp[8] = { x01.x, x01.y, x23.x, x23.y,
                                             x45.x, x45.y, x67.x, x67.y };
#pragma unroll
                for (int rp = 0; rp < 8; ++rp) {
                    acc[rp][0] = fma2(xp[rp], wd0, acc[rp][0]);
                    acc[rp][1] = fma2(xp[rp], wd1, acc[rp][1]);
                }
            }
        }
    }

#pragma unroll
    for (int rp = 0; rp < 8; ++rp) {
        int ra = row0 + rbase + 2 * rp;
        float a0, e0, a1, e1;
        unpack2(acc[rp][0], a0, e0);
        unpack2(acc[rp][1], a1, e1);
        if (ra < n) {
            __half2 p = __floats2half2_rn(a0, a1);
            zh[ra * 32 + lane] = *(unsigned*)&p;
        }
        if (ra + 1 < n) {
            __half2 p = __floats2half2_rn(e0, e1);
            zh[(ra + 1) * 32 + lane] = *(unsigned*)&p;
        }
    }
}

// ---------------------------------------------------------------------------
// Final pooling (64-wide): half-warp per node. Lane16 owns 4 cols (uint2).
// ---------------------------------------------------------------------------

__global__ void __launch_bounds__(256) agg64(const uint2* __restrict__ zh2,
                                             const float* __restrict__ bo,
                                             float* __restrict__ out, int n) {
    int node = (blockIdx.x * blockDim.x + threadIdx.x) >> 4;
    int l    = threadIdx.x & 15;
    if (node >= n) return;

    int s0 = g_row_start[node];
    int s1 = g_row_start[node + 1];

    float4 acc = make_float4(0.f, 0.f, 0.f, 0.f);
    int e = s0;
    for (; e + 4 <= s1; e += 4) {
        int i0 = __ldg(&g_esrc[e]);
        int i1 = __ldg(&g_esrc[e + 1]);
        int i2 = __ldg(&g_esrc[e + 2]);
        int i3 = __ldg(&g_esrc[e + 3]);
        uint2 a = zh2[i0 * 16 + l];
        uint2 b = zh2[i1 * 16 + l];
        uint2 c = zh2[i2 * 16 + l];
        uint2 d = zh2[i3 * 16 + l];
        float2 fa0 = __half22float2(*(__half2*)&a.x);
        float2 fa1 = __half22float2(*(__half2*)&a.y);
        float2 fb0 = __half22float2(*(__half2*)&b.x);
        float2 fb1 = __half22float2(*(__half2*)&b.y);
        float2 fc0 = __half22float2(*(__half2*)&c.x);
        float2 fc1 = __half22float2(*(__half2*)&c.y);
        float2 fd0 = __half22float2(*(__half2*)&d.x);
        float2 fd1 = __half22float2(*(__half2*)&d.y);
        acc.x += (fa0.x + fb0.x) + (fc0.x + fd0.x);
        acc.y += (fa0.y + fb0.y) + (fc0.y + fd0.y);
        acc.z += (fa1.x + fb1.x) + (fc1.x + fd1.x);
        acc.w += (fa1.y + fb1.y) + (fc1.y + fd1.y);
    }
    for (; e < s1; ++e) {
        uint2 a = zh2[__ldg(&g_esrc[e]) * 16 + l];
        float2 fa0 = __half22float2(*(__half2*)&a.x);
        float2 fa1 = __half22float2(*(__half2*)&a.y);
        acc.x += fa0.x; acc.y += fa0.y; acc.z += fa1.x; acc.w += fa1.y;
    }

    float4 bb = ((const float4*)bo)[l];
    ((float4*)out)[node * 16 + l] =
        make_float4(acc.x + bb.x, acc.y + bb.y, acc.z + bb.z, acc.w + bb.w);
}

// ---------------------------------------------------------------------------
// Launcher
// ---------------------------------------------------------------------------

extern "C" void kernel_launch(void* const* d_in, const int* in_sizes, int n_in,
                              void* d_out, int out_size) {
    const float* feats = (const float*)d_in[0];
    const int*   src   = (const int*)  d_in[1];
    const int*   dst   = (const int*)  d_in[2];
    const float* W0    = (const float*)d_in[3];
    const float* b0    = (const float*)d_in[4];
    const float* W1    = (const float*)d_in[5];
    const float* b1    = (const float*)d_in[6];
    const float* W2    = (const float*)d_in[7];
    const float* b2    = (const float*)d_in[8];
    const float* Wo    = (const float*)d_in[9];
    const float* bo    = (const float*)d_in[10];
    float* out = (float*)d_out;

    int n = in_sizes[0] / 128;
    int e = in_sizes[1];

    uint4 *yh4; uint2 *zh2;
    float *h1, *h2, *h3;
    cudaGetSymbolAddress((void**)&yh4, g_yh);
    cudaGetSymbolAddress((void**)&zh2, g_zh);
    cudaGetSymbolAddress((void**)&h1, g_h1);
    cudaGetSymbolAddress((void**)&h2, g_h2);
    cudaGetSymbolAddress((void**)&h3, g_h3);

    int nb = (n + 255) / 256;
    int eb = (e + 255) / 256;
    int sb = (n + SCAN_B - 1) / SCAN_B;

    int gb = (n + 63) / 64;        // gemm blocks (64 rows each, 128 threads)
    int ab = (n + 15) / 16;        // agg blocks (16 half-warps = 16 nodes each)

    // Degrees -> norms -> gemm1 (slot 3, profiled) -> CSR scan/fill.
    k_zero_deg<<<nb, 256>>>(n);
    k_count<<<eb, 256>>>(src, dst, e);
    k_norm<<<nb, 256>>>(n);
    gemm_layer<<<gb, 128>>>(feats, W0, (uint2*)yh4, n);   // launch #3 -> profiled
    k_bsums<<<sb, 1024>>>(n);
    k_scan_bsums<<<1, 1024>>>(sb);
    k_write_csr<<<sb, 1024>>>(n);
    k_fill<<<eb, 256>>>(src, dst, e);

    // Layer 1 aggregation
    agg128<<<ab, 256>>>(yh4, b0, h1, n);
    // Layer 2
    gemm_layer<<<gb, 128>>>(h1, W1, (uint2*)yh4, n);
    agg128<<<ab, 256>>>(yh4, b1, h2, n);
    // Layer 3
    gemm_layer<<<gb, 128>>>(h2, W2, (uint2*)yh4, n);
    agg128<<<ab, 256>>>(yh4, b2, h3, n);

    // Output projection pushed before final pooling
    gemm_z<<<gb, 128>>>(h1, h2, h3, Wo, (unsigned*)zh2, n);
    agg64<<<ab, 256>>>(zh2, bo, out, n);
}